// round 3
// baseline (speedup 1.0000x reference)
#include <cuda_runtime.h>
#include <math.h>

#define NN_MAX 50000
#define S_IN 128
#define S_OUT 128
#define V_IN 16
#define V_OUT 16
#define HID 16
#define SVO 3
#define K_MERGED 153
#define EPSS 1e-8f
#define NREP 32

// Scratch (static device globals)
__device__ float g_vdf[NN_MAX * 12];                 // (N,3,3) padded to 12
__device__ float g_acc[(size_t)NREP * NN_MAX * 16];  // 32 replicas x (9 sums + cnt, pad 16)
__device__ float g_fold[NN_MAX * 12];                // meaned 9 values per node (pad 12)
__device__ float g_WsoT[K_MERGED * 128];             // W_so transposed [k][o]

// ---------------------------------------------------------------------------
// K1: zero replicated accumulators, compute vdf, transpose W_so
// ---------------------------------------------------------------------------
__global__ void k_pre(const float* __restrict__ vector,
                      const float* __restrict__ W_df,
                      const float* __restrict__ W_so,
                      int n_nodes)
{
    int tid = blockIdx.x * blockDim.x + threadIdx.x;

    size_t nzero4 = (size_t)NREP * n_nodes * 4;   // float4 count
    if ((size_t)tid < nzero4)
        reinterpret_cast<float4*>(g_acc)[tid] = make_float4(0.f, 0.f, 0.f, 0.f);

    if (tid < K_MERGED * 128) {
        int k = tid >> 7, o = tid & 127;
        g_WsoT[tid] = W_so[o * K_MERGED + k];
    }

    if (tid >= n_nodes) return;
    int n = tid;

    float v[48];
    const float4* vp = reinterpret_cast<const float4*>(vector + (size_t)n * 48);
#pragma unroll
    for (int q = 0; q < 12; q++) {
        float4 f = vp[q];
        v[q*4+0] = f.x; v[q*4+1] = f.y; v[q*4+2] = f.z; v[q*4+3] = f.w;
    }
#pragma unroll
    for (int j = 0; j < 3; j++) {
        float r0 = 0.f, r1 = 0.f, r2 = 0.f;
#pragma unroll
        for (int i = 0; i < 16; i++) {
            float x = v[i*3 + j];
            r0 += x * __ldg(&W_df[i]);
            r1 += x * __ldg(&W_df[16 + i]);
            r2 += x * __ldg(&W_df[32 + i]);
        }
        g_vdf[(size_t)n*12 + j*3 + 0] = r0;
        g_vdf[(size_t)n*12 + j*3 + 1] = r1;
        g_vdf[(size_t)n*12 + j*3 + 2] = r2;
    }
}

// ---------------------------------------------------------------------------
// K2: per-edge rotation + replicated scatter-add (replica = e & 31)
// ---------------------------------------------------------------------------
__global__ void k_edge(const int* __restrict__ ei,
                       const float* __restrict__ frames,
                       int n_edges, int n_nodes)
{
    int e = blockIdx.x * blockDim.x + threadIdx.x;
    if (e >= n_edges) return;

    int row = ei[e];

    const float4* vp = reinterpret_cast<const float4*>(g_vdf + (size_t)row * 12);
    float4 va = vp[0], vb = vp[1], vc = vp[2];
    float v[9] = { va.x, va.y, va.z, va.w, vb.x, vb.y, vb.z, vb.w, vc.x };

    const float* f = frames + (size_t)e * 9;
    float F[9];
#pragma unroll
    for (int i = 0; i < 9; i++) F[i] = __ldg(&f[i]);

    float loc[9];
#pragma unroll
    for (int x = 0; x < 3; x++)
#pragma unroll
        for (int c = 0; c < 3; c++)
            loc[c*3 + x] = F[x*3+0]*v[0+c] + F[x*3+1]*v[3+c] + F[x*3+2]*v[6+c];

    int rep = e & (NREP - 1);
    float* dst = g_acc + ((size_t)rep * n_nodes + row) * 16;
    asm volatile("red.global.add.v4.f32 [%0], {%1,%2,%3,%4};" ::
                 "l"(dst), "f"(loc[0]), "f"(loc[1]), "f"(loc[2]), "f"(loc[3]) : "memory");
    asm volatile("red.global.add.v4.f32 [%0], {%1,%2,%3,%4};" ::
                 "l"(dst+4), "f"(loc[4]), "f"(loc[5]), "f"(loc[6]), "f"(loc[7]) : "memory");
    asm volatile("red.global.add.v2.f32 [%0], {%1,%2};" ::
                 "l"(dst+8), "f"(loc[8]), "f"(1.0f) : "memory");
}

// ---------------------------------------------------------------------------
// K2b: fold 32 replicas -> meaned 9 values per node (coalesced lines)
// ---------------------------------------------------------------------------
__global__ void k_fold(int n_nodes)
{
    int n = blockIdx.x * blockDim.x + threadIdx.x;
    if (n >= n_nodes) return;

    float sum[9] = {0,0,0,0,0,0,0,0,0};
    float cnt = 0.f;
#pragma unroll 4
    for (int r = 0; r < NREP; r++) {
        const float* a = g_acc + ((size_t)r * n_nodes + n) * 16;
        float4 p0 = reinterpret_cast<const float4*>(a)[0];
        float4 p1 = reinterpret_cast<const float4*>(a)[1];
        float2 p2 = reinterpret_cast<const float2*>(a)[4];
        sum[0] += p0.x; sum[1] += p0.y; sum[2] += p0.z; sum[3] += p0.w;
        sum[4] += p1.x; sum[5] += p1.y; sum[6] += p1.z; sum[7] += p1.w;
        sum[8] += p2.x; cnt += p2.y;
    }
    float inv = 1.0f / fmaxf(cnt, 1.0f);
    float* o = g_fold + (size_t)n * 12;
#pragma unroll
    for (int c = 0; c < 9; c++) o[c] = sum[c] * inv;
}

// ---------------------------------------------------------------------------
// K3: node MLP, 4-node tiles, f32x2 packed GEMM, double-buffered scalar.
// ---------------------------------------------------------------------------
__global__ __launch_bounds__(128, 2) void k_post(
    const float* __restrict__ scalar, const float* __restrict__ vector,
    const float* __restrict__ W_down, const float* __restrict__ b_so,
    const float* __restrict__ W_up, const float* __restrict__ W_g,
    const float* __restrict__ b_g,
    float* __restrict__ out_s, float* __restrict__ out_v, int n_nodes)
{
    const int t = threadIdx.x;

    unsigned long long ww[76];
    float wlast;
#pragma unroll
    for (int kp = 0; kp < 76; kp++) {
        float w0 = g_WsoT[(2*kp)   * 128 + t];
        float w1 = g_WsoT[(2*kp+1) * 128 + t];
        asm("mov.b64 %0, {%1, %2};" : "=l"(ww[kp]) : "f"(w0), "f"(w1));
    }
    wlast = g_WsoT[152 * 128 + t];
    const float bso = b_so[t];

    __shared__ float sWdown[256], sWup[256], sWg[2048], sbg[16];
    __shared__ float mT[2][624];
    __shared__ float vecs[4][48];
    __shared__ float vh[4][48];
    __shared__ float ssm[4][128];
    __shared__ float gsig[4][16];

    if (t < 16) sbg[t] = b_g[t];
#pragma unroll
    for (int i = t; i < 256; i += 128) { sWdown[i] = W_down[i]; sWup[i] = W_up[i]; }
#pragma unroll
    for (int i = t; i < 2048; i += 128) sWg[i] = W_g[i];

    const int ntiles = (n_nodes + 3) >> 2;
    int tile = blockIdx.x;
    int cur = 0;

    if (tile < ntiles) {
        int nb = tile * 4;
#pragma unroll
        for (int nd = 0; nd < 4; nd++) {
            float p = (nb + nd < n_nodes) ? scalar[(size_t)(nb + nd) * 128 + t] : 0.f;
            mT[0][(t >> 1) * 8 + nd * 2 + (t & 1)] = p;
        }
    }

    for (; tile < ntiles; tile += gridDim.x) {
        const int nb = tile * 4;
        float* mbuf = mT[cur];

        // ---- Phase A: vecs + folded scatter-mean ----
        if (t < 48) {
            reinterpret_cast<float4*>(&vecs[0][0])[t] =
                reinterpret_cast<const float4*>(vector + (size_t)nb * 48)[t];
        }
        if (t < 36) {
            int nd = t / 9, c = t - nd * 9;
            int node = nb + nd;
            float val = (node < n_nodes) ? g_fold[(size_t)node * 12 + c] : 0.f;
            int kk = 144 + c;
            if (kk < 152) mbuf[(kk >> 1) * 8 + nd * 2 + (kk & 1)] = val;
            else          mbuf[616 + nd] = val;
        }
        __syncthreads();

        // ---- Phase B: vnorm + vh; prefetch next tile's scalar ----
        if (t < 64) {
            int nd = t >> 4, h = t & 15;
            float a0 = 0.f, a1 = 0.f, a2 = 0.f;
#pragma unroll
            for (int i = 0; i < 16; i++) {
                float wd = sWdown[h * 16 + i];
                a0 += vecs[nd][i*3 + 0] * wd;
                a1 += vecs[nd][i*3 + 1] * wd;
                a2 += vecs[nd][i*3 + 2] * wd;
            }
            vh[nd][0*16 + h] = a0;
            vh[nd][1*16 + h] = a1;
            vh[nd][2*16 + h] = a2;
            int kk = 128 + h;
            mT[cur][(kk >> 1) * 8 + nd * 2 + (kk & 1)] =
                sqrtf(a0*a0 + a1*a1 + a2*a2 + EPSS);
        }
        {
            int ntile = tile + gridDim.x;
            if (ntile < ntiles) {
                int nbn = ntile * 4;
                float* nbuf = mT[cur ^ 1];
#pragma unroll
                for (int nd = 0; nd < 4; nd++) {
                    float p = (nbn + nd < n_nodes) ? scalar[(size_t)(nbn + nd) * 128 + t] : 0.f;
                    nbuf[(t >> 1) * 8 + nd * 2 + (t & 1)] = p;
                }
            }
        }
        __syncthreads();

        // ---- Phase C: packed GEMM (153 x 4 nodes), silu, out_s ----
        {
            unsigned long long acc0 = 0ULL, acc1 = 0ULL, acc2 = 0ULL, acc3 = 0ULL;
#pragma unroll
            for (int kp = 0; kp < 76; kp++) {
                const unsigned long long* m =
                    reinterpret_cast<const unsigned long long*>(mbuf + kp * 8);
                asm("fma.rn.f32x2 %0, %1, %2, %0;" : "+l"(acc0) : "l"(ww[kp]), "l"(m[0]));
                asm("fma.rn.f32x2 %0, %1, %2, %0;" : "+l"(acc1) : "l"(ww[kp]), "l"(m[1]));
                asm("fma.rn.f32x2 %0, %1, %2, %0;" : "+l"(acc2) : "l"(ww[kp]), "l"(m[2]));
                asm("fma.rn.f32x2 %0, %1, %2, %0;" : "+l"(acc3) : "l"(ww[kp]), "l"(m[3]));
            }
            float s[4];
            {
                float lo, hi;
                asm("mov.b64 {%0, %1}, %2;" : "=f"(lo), "=f"(hi) : "l"(acc0));
                s[0] = lo + hi;
                asm("mov.b64 {%0, %1}, %2;" : "=f"(lo), "=f"(hi) : "l"(acc1));
                s[1] = lo + hi;
                asm("mov.b64 {%0, %1}, %2;" : "=f"(lo), "=f"(hi) : "l"(acc2));
                s[2] = lo + hi;
                asm("mov.b64 {%0, %1}, %2;" : "=f"(lo), "=f"(hi) : "l"(acc3));
                s[3] = lo + hi;
            }
#pragma unroll
            for (int nd = 0; nd < 4; nd++) {
                float sv = s[nd] + bso + wlast * mbuf[616 + nd];
                float sil = sv / (1.0f + __expf(-sv));
                ssm[nd][t] = sil;
                if (nb + nd < n_nodes)
                    out_s[(size_t)(nb + nd) * 128 + t] = sil;
            }
        }
        __syncthreads();

        // ---- Phase D: gates then gated vector output ----
        {
            int o2 = t >> 3, part = t & 7;
#pragma unroll
            for (int nd = 0; nd < 4; nd++) {
                float p = 0.f;
#pragma unroll
                for (int k = 0; k < 16; k++)
                    p += ssm[nd][part*16 + k] * sWg[o2*128 + part*16 + k];
                p += __shfl_xor_sync(0xFFFFFFFFu, p, 1);
                p += __shfl_xor_sync(0xFFFFFFFFu, p, 2);
                p += __shfl_xor_sync(0xFFFFFFFFu, p, 4);
                if (part == 0)
                    gsig[nd][o2] = 1.0f / (1.0f + __expf(-(p + sbg[o2])));
            }
        }
        __syncthreads();
        if (t < 48) {
            int o = t / 3, x = t - o * 3;
#pragma unroll
            for (int nd = 0; nd < 4; nd++) {
                float a = 0.f;
#pragma unroll
                for (int h = 0; h < 16; h++)
                    a += vh[nd][x*16 + h] * sWup[o*16 + h];
                if (nb + nd < n_nodes)
                    out_v[(size_t)(nb + nd) * 48 + t] = a * gsig[nd][o];
            }
        }
        __syncthreads();
        cur ^= 1;
    }
}

extern "C" void kernel_launch(void* const* d_in, const int* in_sizes, int n_in,
                              void* d_out, int out_size) {
    const float* scalar = (const float*)d_in[0];
    const float* vector = (const float*)d_in[1];
    const int*   ei     = (const int*)d_in[2];
    const float* frames = (const float*)d_in[3];
    const float* W_down = (const float*)d_in[4];
    const float* W_df   = (const float*)d_in[5];
    const float* W_so   = (const float*)d_in[6];
    const float* b_so   = (const float*)d_in[7];
    const float* W_up   = (const float*)d_in[8];
    const float* W_g    = (const float*)d_in[9];
    const float* b_g    = (const float*)d_in[10];

    int n = in_sizes[0] / S_IN;
    int e = in_sizes[2] / 2;

    float* out_s = (float*)d_out;
    float* out_v = out_s + (size_t)n * S_OUT;

    size_t pre_jobs = (size_t)NREP * n * 4;      // zeroing dominates thread count
    if (pre_jobs < (size_t)n) pre_jobs = n;
    if (pre_jobs < (size_t)K_MERGED * 128) pre_jobs = K_MERGED * 128;

    k_pre<<<(int)((pre_jobs + 255) / 256), 256>>>(vector, W_df, W_so, n);
    k_edge<<<(e + 255) / 256, 256>>>(ei, frames, e, n);
    k_fold<<<(n + 255) / 256, 256>>>(n);
    k_post<<<296, 128>>>(scalar, vector, W_down, b_so, W_up, W_g, b_g,
                         out_s, out_v, n);
}

// round 4
// speedup vs baseline: 1.4491x; 1.4491x over previous
#include <cuda_runtime.h>
#include <math.h>

#define NN_MAX 50000
#define S_IN 128
#define S_OUT 128
#define K_MERGED 153
#define EPSS 1e-8f
#define NREP 8
#define TILE 16

// Scratch (static device globals)
__device__ float g_vdf[NN_MAX * 12];                 // (N,3,3) padded to 12
__device__ float g_acc[(size_t)NREP * NN_MAX * 16];  // replicas x (9 sums + cnt, pad 16)
__device__ float g_fold[NN_MAX * 12];                // meaned 9 values per node (pad 12)
__device__ float g_WsoT[K_MERGED * 128];             // W_so transposed [k][o]

// ---------------------------------------------------------------------------
// K1: zero replicated accumulators, compute vdf, transpose W_so
// ---------------------------------------------------------------------------
__global__ void k_pre(const float* __restrict__ vector,
                      const float* __restrict__ W_df,
                      const float* __restrict__ W_so,
                      int n_nodes)
{
    int tid = blockIdx.x * blockDim.x + threadIdx.x;

    size_t nzero4 = (size_t)NREP * n_nodes * 4;   // float4 count
    if ((size_t)tid < nzero4)
        reinterpret_cast<float4*>(g_acc)[tid] = make_float4(0.f, 0.f, 0.f, 0.f);

    if (tid < K_MERGED * 128) {
        int k = tid >> 7, o = tid & 127;
        g_WsoT[tid] = W_so[o * K_MERGED + k];
    }

    if (tid >= n_nodes) return;
    int n = tid;

    float v[48];
    const float4* vp = reinterpret_cast<const float4*>(vector + (size_t)n * 48);
#pragma unroll
    for (int q = 0; q < 12; q++) {
        float4 f = vp[q];
        v[q*4+0] = f.x; v[q*4+1] = f.y; v[q*4+2] = f.z; v[q*4+3] = f.w;
    }
#pragma unroll
    for (int j = 0; j < 3; j++) {
        float r0 = 0.f, r1 = 0.f, r2 = 0.f;
#pragma unroll
        for (int i = 0; i < 16; i++) {
            float x = v[i*3 + j];
            r0 += x * __ldg(&W_df[i]);
            r1 += x * __ldg(&W_df[16 + i]);
            r2 += x * __ldg(&W_df[32 + i]);
        }
        g_vdf[(size_t)n*12 + j*3 + 0] = r0;
        g_vdf[(size_t)n*12 + j*3 + 1] = r1;
        g_vdf[(size_t)n*12 + j*3 + 2] = r2;
    }
}

// ---------------------------------------------------------------------------
// K2: per-edge rotation + replicated scatter-add (replica = e & 7)
// ---------------------------------------------------------------------------
__global__ void k_edge(const int* __restrict__ ei,
                       const float* __restrict__ frames,
                       int n_edges, int n_nodes)
{
    int e = blockIdx.x * blockDim.x + threadIdx.x;
    if (e >= n_edges) return;

    int row = ei[e];

    const float4* vp = reinterpret_cast<const float4*>(g_vdf + (size_t)row * 12);
    float4 va = vp[0], vb = vp[1], vc = vp[2];
    float v[9] = { va.x, va.y, va.z, va.w, vb.x, vb.y, vb.z, vb.w, vc.x };

    const float* f = frames + (size_t)e * 9;
    float F[9];
#pragma unroll
    for (int i = 0; i < 9; i++) F[i] = __ldg(&f[i]);

    float loc[9];
#pragma unroll
    for (int x = 0; x < 3; x++)
#pragma unroll
        for (int c = 0; c < 3; c++)
            loc[c*3 + x] = F[x*3+0]*v[0+c] + F[x*3+1]*v[3+c] + F[x*3+2]*v[6+c];

    int rep = e & (NREP - 1);
    float* dst = g_acc + ((size_t)rep * n_nodes + row) * 16;
    asm volatile("red.global.add.v4.f32 [%0], {%1,%2,%3,%4};" ::
                 "l"(dst), "f"(loc[0]), "f"(loc[1]), "f"(loc[2]), "f"(loc[3]) : "memory");
    asm volatile("red.global.add.v4.f32 [%0], {%1,%2,%3,%4};" ::
                 "l"(dst+4), "f"(loc[4]), "f"(loc[5]), "f"(loc[6]), "f"(loc[7]) : "memory");
    asm volatile("red.global.add.v2.f32 [%0], {%1,%2};" ::
                 "l"(dst+8), "f"(loc[8]), "f"(1.0f) : "memory");
}

// ---------------------------------------------------------------------------
// K2b: fold replicas -> meaned 9 values per node (coalesced)
// ---------------------------------------------------------------------------
__global__ void k_fold(int n_nodes)
{
    int n = blockIdx.x * blockDim.x + threadIdx.x;
    if (n >= n_nodes) return;

    float sum[9] = {0,0,0,0,0,0,0,0,0};
    float cnt = 0.f;
#pragma unroll
    for (int r = 0; r < NREP; r++) {
        const float* a = g_acc + ((size_t)r * n_nodes + n) * 16;
        float4 p0 = reinterpret_cast<const float4*>(a)[0];
        float4 p1 = reinterpret_cast<const float4*>(a)[1];
        float2 p2 = reinterpret_cast<const float2*>(a)[4];
        sum[0] += p0.x; sum[1] += p0.y; sum[2] += p0.z; sum[3] += p0.w;
        sum[4] += p1.x; sum[5] += p1.y; sum[6] += p1.z; sum[7] += p1.w;
        sum[8] += p2.x; cnt += p2.y;
    }
    float inv = 1.0f / fmaxf(cnt, 1.0f);
    float* o = g_fold + (size_t)n * 12;
#pragma unroll
    for (int c = 0; c < 9; c++) o[c] = sum[c] * inv;
    o[9] = 0.f; o[10] = 0.f; o[11] = 0.f;
}

// ---------------------------------------------------------------------------
// K3: node MLP, 16-node tiles. nd-major merged layout; v2.u64 LDS in GEMM.
// merged row per node: [0:128) scalar, [128:144) vnorm, [144:153) sh; pad 156.
// ---------------------------------------------------------------------------
__global__ __launch_bounds__(128, 2) void k_post(
    const float* __restrict__ scalar, const float* __restrict__ vector,
    const float* __restrict__ W_down, const float* __restrict__ b_so,
    const float* __restrict__ W_up, const float* __restrict__ W_g,
    const float* __restrict__ b_g,
    float* __restrict__ out_s, float* __restrict__ out_v, int n_nodes)
{
    const int t = threadIdx.x;

    // W_so column t packed into 76 u64 k-pairs + leftover k=152
    unsigned long long ww[76];
#pragma unroll
    for (int kp = 0; kp < 76; kp++) {
        float w0 = g_WsoT[(2*kp)   * 128 + t];
        float w1 = g_WsoT[(2*kp+1) * 128 + t];
        asm("mov.b64 %0, {%1, %2};" : "=l"(ww[kp]) : "f"(w0), "f"(w1));
    }
    const float wlast = g_WsoT[152 * 128 + t];
    const float bso = b_so[t];

    // W_g chunk in registers: this thread computes gate partial for
    // (o2 = t>>3) over k in [part*16, part*16+16), part = t&7
    const int o2 = t >> 3, part = t & 7;
    float wg[16];
#pragma unroll
    for (int k = 0; k < 16; k++) wg[k] = W_g[o2 * 128 + part * 16 + k];
    const float bg_o2 = b_g[o2];

    __shared__ __align__(16) float mbuf[TILE * 156];
    __shared__ float vecs[TILE][49];
    __shared__ float vh[TILE][49];
    __shared__ float ssm[TILE][128];
    __shared__ float gsig[TILE][16];
    __shared__ float sWdown[256], sWup[256];

#pragma unroll
    for (int i = t; i < 256; i += 128) { sWdown[i] = W_down[i]; sWup[i] = W_up[i]; }
    __syncthreads();

    const int ntiles = (n_nodes + TILE - 1) / TILE;

    for (int tile = blockIdx.x; tile < ntiles; tile += gridDim.x) {
        const int nb = tile * TILE;

        // ---- Phase A: scalar -> mbuf, vector -> vecs, fold -> mbuf tail ----
#pragma unroll
        for (int nd = 0; nd < TILE; nd++) {
            int node = nb + nd;
            float p = (node < n_nodes) ? scalar[(size_t)node * 128 + t] : 0.f;
            mbuf[nd * 156 + t] = p;
        }
        {
            int q = t;                       // 0..127 then 128..191
            int nd = q / 12, qq = q - nd * 12;
            int node = nb + nd;
            float4 f = (node < n_nodes)
                ? reinterpret_cast<const float4*>(vector)[(size_t)node * 12 + qq]
                : make_float4(0.f,0.f,0.f,0.f);
            int c = qq * 4;
            vecs[nd][c] = f.x; vecs[nd][c+1] = f.y; vecs[nd][c+2] = f.z; vecs[nd][c+3] = f.w;
            if (t < 64) {
                q = t + 128;
                nd = q / 12; qq = q - nd * 12; node = nb + nd;
                f = (node < n_nodes)
                    ? reinterpret_cast<const float4*>(vector)[(size_t)node * 12 + qq]
                    : make_float4(0.f,0.f,0.f,0.f);
                c = qq * 4;
                vecs[nd][c] = f.x; vecs[nd][c+1] = f.y; vecs[nd][c+2] = f.z; vecs[nd][c+3] = f.w;
            }
        }
        if (t < 48) {
            int nd = t / 3, q = t - nd * 3;
            int node = nb + nd;
            float4 f = (node < n_nodes)
                ? reinterpret_cast<const float4*>(g_fold)[(size_t)node * 3 + q]
                : make_float4(0.f,0.f,0.f,0.f);
            int c = q * 4;
            float vv[4] = { f.x, f.y, f.z, f.w };
#pragma unroll
            for (int j = 0; j < 4; j++)
                if (c + j < 9) mbuf[nd * 156 + 144 + c + j] = vv[j];
        }
        __syncthreads();

        // ---- Phase B: vh + vnorm (thread: nd = t>>3, h = t&7 and +8) ----
        {
            int nd = t >> 3, h0 = t & 7;
#pragma unroll
            for (int hh = 0; hh < 2; hh++) {
                int h = h0 + hh * 8;
                float a0 = 0.f, a1 = 0.f, a2 = 0.f;
#pragma unroll
                for (int i = 0; i < 16; i++) {
                    float wd = sWdown[h * 16 + i];
                    a0 += vecs[nd][i*3 + 0] * wd;
                    a1 += vecs[nd][i*3 + 1] * wd;
                    a2 += vecs[nd][i*3 + 2] * wd;
                }
                vh[nd][0*16 + h] = a0;
                vh[nd][1*16 + h] = a1;
                vh[nd][2*16 + h] = a2;
                mbuf[nd * 156 + 128 + h] = sqrtf(a0*a0 + a1*a1 + a2*a2 + EPSS);
            }
        }
        __syncthreads();

        // ---- Phase C: GEMM 153 x 16 nodes via f32x2, v2.u64 shared loads ----
        {
            unsigned long long acc[TILE];
#pragma unroll
            for (int nd = 0; nd < TILE; nd++) acc[nd] = 0ULL;

            const ulonglong2* mp = reinterpret_cast<const ulonglong2*>(mbuf);
#pragma unroll 2
            for (int kp2 = 0; kp2 < 38; kp2++) {   // covers k = 0..151
                unsigned long long w0 = ww[2*kp2], w1 = ww[2*kp2 + 1];
#pragma unroll
                for (int nd = 0; nd < TILE; nd++) {
                    ulonglong2 m = mp[nd * 39 + kp2];
                    asm("fma.rn.f32x2 %0, %1, %2, %0;" : "+l"(acc[nd]) : "l"(w0), "l"(m.x));
                    asm("fma.rn.f32x2 %0, %1, %2, %0;" : "+l"(acc[nd]) : "l"(w1), "l"(m.y));
                }
            }
#pragma unroll
            for (int nd = 0; nd < TILE; nd++) {
                float lo, hi;
                asm("mov.b64 {%0, %1}, %2;" : "=f"(lo), "=f"(hi) : "l"(acc[nd]));
                float sv = lo + hi + bso + wlast * mbuf[nd * 156 + 152];
                float sil = sv / (1.0f + __expf(-sv));
                ssm[nd][t] = sil;
                int node = nb + nd;
                if (node < n_nodes)
                    out_s[(size_t)node * 128 + t] = sil;
            }
        }
        __syncthreads();

        // ---- Phase D: gates (W_g in regs, shfl reduce over 8 partials) ----
#pragma unroll
        for (int nd = 0; nd < TILE; nd++) {
            float p = 0.f;
#pragma unroll
            for (int k = 0; k < 16; k++)
                p += ssm[nd][part * 16 + k] * wg[k];
            p += __shfl_xor_sync(0xFFFFFFFFu, p, 1);
            p += __shfl_xor_sync(0xFFFFFFFFu, p, 2);
            p += __shfl_xor_sync(0xFFFFFFFFu, p, 4);
            float g = 1.0f / (1.0f + __expf(-(p + bg_o2)));
            if (part == 0) gsig[nd][o2] = g;
        }
        __syncthreads();

        // ---- Phase E: gated vector output (768 items, 6 per thread) ----
#pragma unroll
        for (int r = 0; r < 6; r++) {
            int i = t + 128 * r;
            int nd = i / 48, j = i - nd * 48;
            int o = j / 3, x = j - o * 3;
            float a = 0.f;
#pragma unroll
            for (int h = 0; h < 16; h++)
                a += vh[nd][x*16 + h] * sWup[o*16 + h];
            int node = nb + nd;
            if (node < n_nodes)
                out_v[(size_t)node * 48 + j] = a * gsig[nd][o];
        }
        __syncthreads();
    }
}

extern "C" void kernel_launch(void* const* d_in, const int* in_sizes, int n_in,
                              void* d_out, int out_size) {
    const float* scalar = (const float*)d_in[0];
    const float* vector = (const float*)d_in[1];
    const int*   ei     = (const int*)d_in[2];
    const float* frames = (const float*)d_in[3];
    const float* W_down = (const float*)d_in[4];
    const float* W_df   = (const float*)d_in[5];
    const float* W_so   = (const float*)d_in[6];
    const float* b_so   = (const float*)d_in[7];
    const float* W_up   = (const float*)d_in[8];
    const float* W_g    = (const float*)d_in[9];
    const float* b_g    = (const float*)d_in[10];

    int n = in_sizes[0] / S_IN;
    int e = in_sizes[2] / 2;

    float* out_s = (float*)d_out;
    float* out_v = out_s + (size_t)n * S_OUT;

    size_t pre_jobs = (size_t)NREP * n * 4;
    if (pre_jobs < (size_t)n) pre_jobs = n;
    if (pre_jobs < (size_t)K_MERGED * 128) pre_jobs = K_MERGED * 128;

    k_pre<<<(int)((pre_jobs + 255) / 256), 256>>>(vector, W_df, W_so, n);
    k_edge<<<(e + 255) / 256, 256>>>(ei, frames, e, n);
    k_fold<<<(n + 255) / 256, 256>>>(n);
    k_post<<<296, 128>>>(scalar, vector, W_down, b_so, W_up, W_g, b_g,
                         out_s, out_v, n);
}

// round 5
// speedup vs baseline: 1.5620x; 1.0779x over previous
#include <cuda_runtime.h>
#include <math.h>

#define NN_MAX 50000
#define S_IN 128
#define S_OUT 128
#define K_MERGED 153
#define EPSS 1e-8f
#define NREP 8
#define TILE 16

// Scratch (static device globals)
__device__ float g_vdf[NN_MAX * 12];
__device__ float g_acc[(size_t)NREP * NN_MAX * 16];
__device__ float g_fold[NN_MAX * 12];
__device__ float g_WsoT[K_MERGED * 128];

// ---------------------------------------------------------------------------
// K1: zero replicated accumulators, compute vdf, transpose W_so
// ---------------------------------------------------------------------------
__global__ void k_pre(const float* __restrict__ vector,
                      const float* __restrict__ W_df,
                      const float* __restrict__ W_so,
                      int n_nodes)
{
    int tid = blockIdx.x * blockDim.x + threadIdx.x;

    size_t nzero4 = (size_t)NREP * n_nodes * 4;
    if ((size_t)tid < nzero4)
        reinterpret_cast<float4*>(g_acc)[tid] = make_float4(0.f, 0.f, 0.f, 0.f);

    if (tid < K_MERGED * 128) {
        int k = tid >> 7, o = tid & 127;
        g_WsoT[tid] = W_so[o * K_MERGED + k];
    }

    if (tid >= n_nodes) return;
    int n = tid;

    float v[48];
    const float4* vp = reinterpret_cast<const float4*>(vector + (size_t)n * 48);
#pragma unroll
    for (int q = 0; q < 12; q++) {
        float4 f = vp[q];
        v[q*4+0] = f.x; v[q*4+1] = f.y; v[q*4+2] = f.z; v[q*4+3] = f.w;
    }
#pragma unroll
    for (int j = 0; j < 3; j++) {
        float r0 = 0.f, r1 = 0.f, r2 = 0.f;
#pragma unroll
        for (int i = 0; i < 16; i++) {
            float x = v[i*3 + j];
            r0 += x * __ldg(&W_df[i]);
            r1 += x * __ldg(&W_df[16 + i]);
            r2 += x * __ldg(&W_df[32 + i]);
        }
        g_vdf[(size_t)n*12 + j*3 + 0] = r0;
        g_vdf[(size_t)n*12 + j*3 + 1] = r1;
        g_vdf[(size_t)n*12 + j*3 + 2] = r2;
    }
}

// ---------------------------------------------------------------------------
// K2: per-edge rotation + replicated scatter-add (replica = e & 7)
// ---------------------------------------------------------------------------
__global__ void k_edge(const int* __restrict__ ei,
                       const float* __restrict__ frames,
                       int n_edges, int n_nodes)
{
    int e = blockIdx.x * blockDim.x + threadIdx.x;
    if (e >= n_edges) return;

    int row = ei[e];

    const float4* vp = reinterpret_cast<const float4*>(g_vdf + (size_t)row * 12);
    float4 va = vp[0], vb = vp[1], vc = vp[2];
    float v[9] = { va.x, va.y, va.z, va.w, vb.x, vb.y, vb.z, vb.w, vc.x };

    const float* f = frames + (size_t)e * 9;
    float F[9];
#pragma unroll
    for (int i = 0; i < 9; i++) F[i] = __ldg(&f[i]);

    float loc[9];
#pragma unroll
    for (int x = 0; x < 3; x++)
#pragma unroll
        for (int c = 0; c < 3; c++)
            loc[c*3 + x] = F[x*3+0]*v[0+c] + F[x*3+1]*v[3+c] + F[x*3+2]*v[6+c];

    int rep = e & (NREP - 1);
    float* dst = g_acc + ((size_t)rep * n_nodes + row) * 16;
    asm volatile("red.global.add.v4.f32 [%0], {%1,%2,%3,%4};" ::
                 "l"(dst), "f"(loc[0]), "f"(loc[1]), "f"(loc[2]), "f"(loc[3]) : "memory");
    asm volatile("red.global.add.v4.f32 [%0], {%1,%2,%3,%4};" ::
                 "l"(dst+4), "f"(loc[4]), "f"(loc[5]), "f"(loc[6]), "f"(loc[7]) : "memory");
    asm volatile("red.global.add.v2.f32 [%0], {%1,%2};" ::
                 "l"(dst+8), "f"(loc[8]), "f"(1.0f) : "memory");
}

// ---------------------------------------------------------------------------
// K2b: fold replicas -> meaned 9 values per node
// ---------------------------------------------------------------------------
__global__ void k_fold(int n_nodes)
{
    int n = blockIdx.x * blockDim.x + threadIdx.x;
    if (n >= n_nodes) return;

    float sum[9] = {0,0,0,0,0,0,0,0,0};
    float cnt = 0.f;
#pragma unroll
    for (int r = 0; r < NREP; r++) {
        const float* a = g_acc + ((size_t)r * n_nodes + n) * 16;
        float4 p0 = reinterpret_cast<const float4*>(a)[0];
        float4 p1 = reinterpret_cast<const float4*>(a)[1];
        float2 p2 = reinterpret_cast<const float2*>(a)[4];
        sum[0] += p0.x; sum[1] += p0.y; sum[2] += p0.z; sum[3] += p0.w;
        sum[4] += p1.x; sum[5] += p1.y; sum[6] += p1.z; sum[7] += p1.w;
        sum[8] += p2.x; cnt += p2.y;
    }
    float inv = 1.0f / fmaxf(cnt, 1.0f);
    float* o = g_fold + (size_t)n * 12;
#pragma unroll
    for (int c = 0; c < 9; c++) o[c] = sum[c] * inv;
    o[9] = 0.f; o[10] = 0.f; o[11] = 0.f;
}

// ---------------------------------------------------------------------------
// K3: node MLP. 256 threads, split-K GEMM (each half-block owns 38 k-pairs),
// 16-node tiles, f32x2 FMA, v2.u64 shared loads, 32 warps/SM.
// merged row per node: [0:128) scalar, [128:144) vnorm, [144:153) sh; pad 156.
// ---------------------------------------------------------------------------
__global__ __launch_bounds__(256, 2) void k_post(
    const float* __restrict__ scalar, const float* __restrict__ vector,
    const float* __restrict__ W_down, const float* __restrict__ b_so,
    const float* __restrict__ W_up, const float* __restrict__ W_g,
    const float* __restrict__ b_g,
    float* __restrict__ out_s, float* __restrict__ out_v, int n_nodes)
{
    const int t = threadIdx.x;
    const int col = t & 127;
    const int half = t >> 7;

    // this thread's 38 W_so k-pairs (k = half*76 .. half*76+75, paired)
    unsigned long long ww[38];
#pragma unroll
    for (int kp = 0; kp < 38; kp++) {
        int kk = half * 38 + kp;
        float w0 = g_WsoT[(2*kk)   * 128 + col];
        float w1 = g_WsoT[(2*kk+1) * 128 + col];
        asm("mov.b64 %0, {%1, %2};" : "=l"(ww[kp]) : "f"(w0), "f"(w1));
    }
    const float wlast = g_WsoT[152 * 128 + col];
    const float bso = b_so[col];

    // gates: output go = t>>4 (0..15), partial gpart = t&15 over 8 k's
    const int go = t >> 4, gpart = t & 15;
    float wg[8];
#pragma unroll
    for (int k = 0; k < 8; k++) wg[k] = W_g[go * 128 + gpart * 8 + k];
    const float bg = b_g[go];

    __shared__ __align__(16) float mbuf[TILE * 156];
    __shared__ float pbuf[2][TILE * 128];
    __shared__ float vecs[TILE][49];
    __shared__ float vh[TILE][49];
    __shared__ float ssm[TILE][128];
    __shared__ float gsig[TILE][16];
    __shared__ float sWdown[256], sWup[256];

    sWdown[t] = W_down[t];
    sWup[t] = W_up[t];
    __syncthreads();

    const int ntiles = (n_nodes + TILE - 1) / TILE;

    for (int tile = blockIdx.x; tile < ntiles; tile += gridDim.x) {
        const int nb = tile * TILE;

        // ---- Phase A: loads ----
#pragma unroll
        for (int r = 0; r < 8; r++) {
            int nd = half + r * 2;
            int node = nb + nd;
            float p = (node < n_nodes) ? scalar[(size_t)node * 128 + col] : 0.f;
            mbuf[nd * 156 + col] = p;
        }
        if (t < 192) {
            int nd = t / 12, qq = t - nd * 12;
            int node = nb + nd;
            float4 f = (node < n_nodes)
                ? reinterpret_cast<const float4*>(vector)[(size_t)node * 12 + qq]
                : make_float4(0.f,0.f,0.f,0.f);
            int c = qq * 4;
            vecs[nd][c] = f.x; vecs[nd][c+1] = f.y; vecs[nd][c+2] = f.z; vecs[nd][c+3] = f.w;
        }
        if (t < 48) {
            int nd = t / 3, q = t - nd * 3;
            int node = nb + nd;
            float4 f = (node < n_nodes)
                ? reinterpret_cast<const float4*>(g_fold)[(size_t)node * 3 + q]
                : make_float4(0.f,0.f,0.f,0.f);
            int c = q * 4;
            float vv[4] = { f.x, f.y, f.z, f.w };
#pragma unroll
            for (int j = 0; j < 4; j++)
                if (c + j < 9) mbuf[nd * 156 + 144 + c + j] = vv[j];
        }
        __syncthreads();

        // ---- Phase B: vh + vnorm (nd = t>>4, h = t&15) ----
        {
            int nd = t >> 4, h = t & 15;
            float a0 = 0.f, a1 = 0.f, a2 = 0.f;
#pragma unroll
            for (int i = 0; i < 16; i++) {
                float wd = sWdown[h * 16 + i];
                a0 += vecs[nd][i*3 + 0] * wd;
                a1 += vecs[nd][i*3 + 1] * wd;
                a2 += vecs[nd][i*3 + 2] * wd;
            }
            vh[nd][0*16 + h] = a0;
            vh[nd][1*16 + h] = a1;
            vh[nd][2*16 + h] = a2;
            mbuf[nd * 156 + 128 + h] = sqrtf(a0*a0 + a1*a1 + a2*a2 + EPSS);
        }
        __syncthreads();

        // ---- Phase C: split-K GEMM, two passes of 8 nodes ----
        {
            const ulonglong2* mp = reinterpret_cast<const ulonglong2*>(mbuf);
            const int vbase = half * 19;   // 19 v2 loads cover this half's 38 pairs
#pragma unroll
            for (int pass = 0; pass < 2; pass++) {
                unsigned long long acc[8];
#pragma unroll
                for (int i = 0; i < 8; i++) acc[i] = 0ULL;
#pragma unroll 2
                for (int kq = 0; kq < 19; kq++) {
                    unsigned long long w0 = ww[2*kq], w1 = ww[2*kq + 1];
#pragma unroll
                    for (int i = 0; i < 8; i++) {
                        int nd = pass * 8 + i;
                        ulonglong2 m = mp[nd * 39 + vbase + kq];
                        asm("fma.rn.f32x2 %0, %1, %2, %0;" : "+l"(acc[i]) : "l"(w0), "l"(m.x));
                        asm("fma.rn.f32x2 %0, %1, %2, %0;" : "+l"(acc[i]) : "l"(w1), "l"(m.y));
                    }
                }
#pragma unroll
                for (int i = 0; i < 8; i++) {
                    int nd = pass * 8 + i;
                    float lo, hi;
                    asm("mov.b64 {%0, %1}, %2;" : "=f"(lo), "=f"(hi) : "l"(acc[i]));
                    pbuf[half][nd * 128 + col] = lo + hi;
                }
            }
        }
        __syncthreads();

        // ---- combine halves: each half finalizes 8 nodes ----
        {
            int base = half * 8;
#pragma unroll
            for (int i = 0; i < 8; i++) {
                int nd = base + i;
                float sv = pbuf[0][nd * 128 + col] + pbuf[1][nd * 128 + col]
                         + bso + wlast * mbuf[nd * 156 + 152];
                float sil = sv / (1.0f + __expf(-sv));
                ssm[nd][col] = sil;
                int node = nb + nd;
                if (node < n_nodes)
                    out_s[(size_t)node * 128 + col] = sil;
            }
        }
        __syncthreads();

        // ---- Phase D: gates (16 threads per output, 16-lane shfl reduce) ----
#pragma unroll
        for (int nd = 0; nd < TILE; nd++) {
            float p = 0.f;
#pragma unroll
            for (int k = 0; k < 8; k++)
                p += ssm[nd][gpart * 8 + k] * wg[k];
            p += __shfl_xor_sync(0xFFFFFFFFu, p, 1);
            p += __shfl_xor_sync(0xFFFFFFFFu, p, 2);
            p += __shfl_xor_sync(0xFFFFFFFFu, p, 4);
            p += __shfl_xor_sync(0xFFFFFFFFu, p, 8);
            if (gpart == 0)
                gsig[nd][go] = 1.0f / (1.0f + __expf(-(p + bg)));
        }
        __syncthreads();

        // ---- Phase E: gated vector output (768 items, 3 per thread) ----
#pragma unroll
        for (int r = 0; r < 3; r++) {
            int i = t + 256 * r;
            int nd = i / 48, j = i - nd * 48;
            int o = j / 3, x = j - o * 3;
            float a = 0.f;
#pragma unroll
            for (int h = 0; h < 16; h++)
                a += vh[nd][x*16 + h] * sWup[o*16 + h];
            int node = nb + nd;
            if (node < n_nodes)
                out_v[(size_t)node * 48 + j] = a * gsig[nd][o];
        }
        __syncthreads();
    }
}

extern "C" void kernel_launch(void* const* d_in, const int* in_sizes, int n_in,
                              void* d_out, int out_size) {
    const float* scalar = (const float*)d_in[0];
    const float* vector = (const float*)d_in[1];
    const int*   ei     = (const int*)d_in[2];
    const float* frames = (const float*)d_in[3];
    const float* W_down = (const float*)d_in[4];
    const float* W_df   = (const float*)d_in[5];
    const float* W_so   = (const float*)d_in[6];
    const float* b_so   = (const float*)d_in[7];
    const float* W_up   = (const float*)d_in[8];
    const float* W_g    = (const float*)d_in[9];
    const float* b_g    = (const float*)d_in[10];

    int n = in_sizes[0] / S_IN;
    int e = in_sizes[2] / 2;

    float* out_s = (float*)d_out;
    float* out_v = out_s + (size_t)n * S_OUT;

    size_t pre_jobs = (size_t)NREP * n * 4;
    if (pre_jobs < (size_t)n) pre_jobs = n;
    if (pre_jobs < (size_t)K_MERGED * 128) pre_jobs = K_MERGED * 128;

    k_pre<<<(int)((pre_jobs + 255) / 256), 256>>>(vector, W_df, W_so, n);
    k_edge<<<(e + 255) / 256, 256>>>(ei, frames, e, n);
    k_fold<<<(n + 255) / 256, 256>>>(n);
    k_post<<<296, 256>>>(scalar, vector, W_down, b_so, W_up, W_g, b_g,
                         out_s, out_v, n);
}